// round 16
// baseline (speedup 1.0000x reference)
#include <cuda_runtime.h>
#include <cstdint>
#include <cstddef>

#define BATCH 4096
#define T_SEQ 512
#define SDIM  16
#define ODIM  8
#define IDIM  4
#define RS    8
#define CH    64
#define LCH   8
#define NB    2
#define TPB   128
#define RTPB  256
#define NTYPE 2

typedef unsigned long long ull;

__device__ float g_M [RS*256];
__device__ float g_Kg[RS*128];
__device__ float g_Ng[RS*64];
__device__ float g_Phi[NTYPE*256];
__device__ float g_W  [NTYPE*16*96];            // [type][s][j*12 + q] (q: 0..7 z, 8..11 u)
__device__ float g_d [(size_t)CH*SDIM*BATCH];   // [c][s][b]
__device__ float g_xs[(size_t)CH*SDIM*BATCH];   // [c][s][b]

// ---------- f32x2 helpers ----------
__device__ __forceinline__ ull fpair(float a, float b){
  ull r; asm("mov.b64 %0, {%1,%2};" : "=l"(r) : "f"(a), "f"(b)); return r;
}
__device__ __forceinline__ ull fdup(float a){ return fpair(a,a); }
__device__ __forceinline__ void unpack2(ull p, float& a, float& b){
  asm("mov.b64 {%0,%1}, %2;" : "=f"(a), "=f"(b) : "l"(p));
}
__device__ __forceinline__ void ffma2(ull& d, ull a, ull b){
  asm("fma.rn.f32x2 %0, %1, %2, %0;" : "+l"(d) : "l"(a), "l"(b));
}

// ---------- 256-bit global memory ops (sm_100+) ----------
__device__ __forceinline__ void ldg256(float* r, const float* p){
  asm("ld.global.v8.f32 {%0,%1,%2,%3,%4,%5,%6,%7}, [%8];"
      : "=f"(r[0]),"=f"(r[1]),"=f"(r[2]),"=f"(r[3]),
        "=f"(r[4]),"=f"(r[5]),"=f"(r[6]),"=f"(r[7])
      : "l"(p));
}
__device__ __forceinline__ void stg256(float* p, const float* r){
  asm volatile("st.global.v8.f32 [%0], {%1,%2,%3,%4,%5,%6,%7,%8};"
      :: "l"(p),
         "f"(r[0]),"f"(r[1]),"f"(r[2]),"f"(r[3]),
         "f"(r[4]),"f"(r[5]),"f"(r[6]),"f"(r[7])
      : "memory");
}

// K1: Riccati (8 exact steps, Gauss-Jordan S-inverse) + W/Phi composition. 1 block, 256 thr.
__global__ void riccati_kernel(const float* __restrict__ A_, const float* __restrict__ B_,
                               const float* __restrict__ C_, const float* __restrict__ Q_,
                               const float* __restrict__ R_)
{
  __shared__ float sA[256], sQ[256], sC[128], sB[64], sR[64], sCA[128], sCB[32];
  __shared__ float P[256], Tm[256], Pp[256], CP[128], S8[64], Inv8[64], KK[128];
  __shared__ float BufA[256], BufB[256];
  __shared__ float sMh[RS*256], sKh[RS*128], sNh[RS*64];
  const int t = threadIdx.x;
  const int s = t>>4, j = t&15;

  sA[t]=A_[t]; sQ[t]=Q_[t];
  P[t] = (s==j)?1.f:0.f;
  if (t<128) sC[t]=C_[t];
  if (t<64){ sB[t]=B_[t]; sR[t]=R_[t]; }
  __syncthreads();
  if (t<128){ int o=t>>4, jj=t&15; float a=0.f;
    #pragma unroll
    for(int m=0;m<16;m++) a+=sC[o*16+m]*sA[m*16+jj];
    sCA[t]=a; }
  if (t<32){ int o=t>>2, ii=t&3; float a=0.f;
    #pragma unroll
    for(int m=0;m<16;m++) a+=sC[o*16+m]*sB[m*4+ii];
    sCB[t]=a; }
  __syncthreads();

  for (int k=0;k<RS;k++){
    { float a=0.f;                                    // Tm = A @ P
      #pragma unroll
      for(int m=0;m<16;m++) a+=sA[s*16+m]*P[m*16+j];
      Tm[t]=a; }
    __syncthreads();
    { float a=sQ[t];                                  // Pp = Tm A^T + Q
      #pragma unroll
      for(int m=0;m<16;m++) a+=Tm[s*16+m]*sA[j*16+m];
      Pp[t]=a; }
    __syncthreads();
    if (t<128){ int o=t>>4, jj=t&15; float a=0.f;     // CP = C @ Pp
      #pragma unroll
      for(int m=0;m<16;m++) a+=sC[o*16+m]*Pp[m*16+jj];
      CP[t]=a; }
    __syncthreads();
    if (t<64){ int o=t>>3, p=t&7; float a=sR[t];      // S = CP C^T + R
      #pragma unroll
      for(int m=0;m<16;m++) a+=CP[o*16+m]*sC[p*16+m];
      S8[t]=a;
      Inv8[t]=(o==p)?1.f:0.f; }
    __syncthreads();
    for (int p=0;p<8;p++){                            // Gauss-Jordan (SPD, no pivoting)
      if (t<64 && (t>>3)==p){
        float rp = 1.f/S8[p*8+p];
        S8[t]*=rp; Inv8[t]*=rp;
      }
      __syncthreads();
      float f=0.f, spc=0.f, sic=0.f, so=0.f, io=0.f;
      if (t<64){
        f=S8[(t>>3)*8+p]; spc=S8[p*8+(t&7)]; sic=Inv8[p*8+(t&7)]; so=S8[t]; io=Inv8[t]; }
      __syncthreads();
      if (t<64 && (t>>3)!=p){
        S8[t]=so-f*spc; Inv8[t]=io-f*sic;
      }
      __syncthreads();
    }
    if (t<128){ int ss=t>>3, o=t&7; float a=0.f;      // K = CP^T Sinv
      #pragma unroll
      for(int p=0;p<8;p++) a+=CP[p*16+ss]*Inv8[p*8+o];
      KK[t]=a; }
    __syncthreads();
    { float a=Pp[t], mg=sA[t];                        // P_post, M_k
      #pragma unroll
      for(int o=0;o<8;o++){ float kv=KK[s*8+o]; a-=kv*CP[o*16+j]; mg-=kv*sCA[o*16+j]; }
      P[t]=a;
      sMh[k*256+t]=mg; g_M[k*256+t]=mg; }
    if (t<128){ sKh[k*128+t]=KK[t]; g_Kg[k*128+t]=KK[t]; }
    if (t<64){ int ss=t>>2, ii=t&3; float a=sB[t];    // N_k
      #pragma unroll
      for(int o=0;o<8;o++) a-=KK[ss*8+o]*sCB[o*4+ii];
      sNh[k*64+t]=a; g_Ng[k*64+t]=a; }
    __syncthreads();
  }

  for (int tt=0; tt<NTYPE; tt++){                     // W + Phi per chunk type
    float* Sb = BufA; float* Sn = BufB;
    Sb[t] = (s==j)?1.f:0.f;
    __syncthreads();
    for (int jj=LCH-1; jj>=0; jj--){
      const int k = (tt==0)? jj : (RS-1);
      if (t<128){ int ss=t>>3, o=t&7; float a=0.f;    // Wz
        #pragma unroll
        for(int m=0;m<16;m++) a+=Sb[ss*16+m]*sKh[k*128+m*8+o];
        g_W[(tt*16+ss)*96 + jj*12 + o] = a; }
      else { int e=t-128; int ss=e>>2, ii=e&3;        // Wu
        if (e<64){ float a=0.f;
          #pragma unroll
          for(int m=0;m<16;m++) a+=Sb[ss*16+m]*sNh[k*64+m*4+ii];
          g_W[(tt*16+ss)*96 + jj*12 + 8 + ii] = a; } }
      { float a=0.f;                                  // S = S @ M_k
        #pragma unroll
        for(int m=0;m<16;m++) a+=Sb[s*16+m]*sMh[k*256+m*16+j];
        Sn[t]=a; }
      __syncthreads();
      float* tmp=Sb; Sb=Sn; Sn=tmp;
    }
    g_Phi[tt*256+t]=Sb[t];
    __syncthreads();
  }
}

// P1: chunk response from zero state; TPB=256 for higher resident-warp count.
__global__ void __launch_bounds__(RTPB) resp_kernel(const float* __restrict__ obs,
                                                    const float* __restrict__ u)
{
  __shared__ ull sW[16*96];
  const int c  = blockIdx.y;
  const int tt = (c==0)?0:1;
  for (int idx=threadIdx.x; idx<16*96; idx+=RTPB)
    sW[idx] = fdup(g_W[tt*16*96 + idx]);
  const int b0 = (blockIdx.x*RTPB + threadIdx.x)*NB;
  const int k0 = c*LCH;
  ull acc[SDIM];
  #pragma unroll
  for (int s=0;s<SDIM;s++) acc[s]=0ull;
  __syncthreads();

  const float* ob0 = obs + ((size_t)b0*T_SEQ + k0)*ODIM;
  const float* ob1 = ob0 + (size_t)T_SEQ*ODIM;
  const float* uu0 = u   + ((size_t)b0*T_SEQ + k0)*IDIM;
  const float* uu1 = uu0 + (size_t)T_SEQ*IDIM;

  for (int jj=0;jj<LCH;jj+=2){
    float ua0[8], ua1[8];
    ldg256(ua0, uu0 + jj*IDIM);
    ldg256(ua1, uu1 + jj*IDIM);
    #pragma unroll
    for (int h=0;h<2;h++){
      const int j2 = jj+h;
      float z0[8], z1[8];
      ldg256(z0, ob0 + j2*ODIM);
      ldg256(z1, ob1 + j2*ODIM);
      ull ip[12];
      #pragma unroll
      for (int q=0;q<8;q++) ip[q]=fpair(z0[q],z1[q]);
      #pragma unroll
      for (int q=0;q<4;q++) ip[8+q]=fpair(ua0[h*4+q],ua1[h*4+q]);
      #pragma unroll
      for (int s=0;s<SDIM;s++){
        const ulonglong2* Wr = (const ulonglong2*)&sW[s*96 + j2*12];
        ull a = acc[s];
        #pragma unroll
        for (int q=0;q<6;q++){
          ulonglong2 w = Wr[q];
          ffma2(a, w.x, ip[2*q]);
          ffma2(a, w.y, ip[2*q+1]);
        }
        acc[s]=a;
      }
    }
  }
  #pragma unroll
  for (int s=0;s<SDIM;s++)
    *(ull*)&g_d[((size_t)(c*SDIM+s))*BATCH + b0] = acc[s];
}

// P2: one thread per (batch, state). 8 batches x 16 states per block, smem x-exchange.
__global__ void __launch_bounds__(TPB) pass2_kernel(const float* __restrict__ x0)
{
  __shared__ float sPhi[NTYPE*256];
  __shared__ float sX[TPB];
  for (int e=threadIdx.x; e<NTYPE*256; e+=TPB) sPhi[e]=g_Phi[e];
  const int t  = threadIdx.x;
  const int s  = t>>3;
  const int bl = t&7;
  const int b  = blockIdx.x*8 + bl;
  float x = x0[s];
  __syncthreads();
  g_xs[(size_t)s*BATCH + b] = x;
  for (int c=1;c<CH;c++){
    sX[s*8+bl] = x;
    const float* Phi = &sPhi[((c-1==0)?0:1)*256 + s*16];
    float dd = g_d[((size_t)((c-1)*16+s))*BATCH + b];
    __syncthreads();
    float a = dd;
    #pragma unroll
    for (int jj=0;jj<16;jj++) a += Phi[jj]*sX[jj*8+bl];
    __syncthreads();
    x = a;
    g_xs[((size_t)(c*16+s))*BATCH + b] = x;
  }
}

// P3: R14 body; occupancy 5 blocks/SM via launch bounds.
__global__ void __launch_bounds__(TPB, 5) pass3_kernel(const float* __restrict__ obs,
                                                       const float* __restrict__ u,
                                                       float* __restrict__ out)
{
  __shared__ ull sM[LCH*256], sK[LCH*128], sN[LCH*64];  // 28KB
  const int tid = threadIdx.x;
  const int c  = blockIdx.y;
  const bool trans = (c==0);
  const int nset = trans ? LCH : 1;
  for (int idx=tid; idx<nset*256; idx+=TPB){
    int i=idx>>8, e=idx&255; int kk = trans ? i : (RS-1);
    sM[idx]=fdup(g_M[kk*256+e]);
  }
  for (int idx=tid; idx<nset*128; idx+=TPB){
    int i=idx>>7, e=idx&127; int kk = trans ? i : (RS-1);
    sK[idx]=fdup(g_Kg[kk*128+e]);
  }
  for (int idx=tid; idx<nset*64; idx+=TPB){
    int i=idx>>6, e=idx&63; int kk = trans ? i : (RS-1);
    sN[idx]=fdup(g_Ng[kk*64+e]);
  }
  const int b0 = blockIdx.x*(TPB*NB) + tid*NB;
  const int k0 = c*LCH;
  ull xp[SDIM];
  #pragma unroll
  for (int s=0;s<SDIM;s++)
    xp[s] = *(const ull*)&g_xs[((size_t)(c*SDIM+s))*BATCH + b0];
  __syncthreads();

  const float* ob0 = obs + ((size_t)b0*T_SEQ + k0)*ODIM;
  const float* ob1 = ob0 + (size_t)T_SEQ*ODIM;
  const float* uu0 = u   + ((size_t)b0*T_SEQ + k0)*IDIM;
  const float* uu1 = uu0 + (size_t)T_SEQ*IDIM;

  for (int i=0;i<LCH;i++){
    const int mi = trans ? i : 0;
    float z0[8], z1[8];
    ldg256(z0, ob0 + i*ODIM);
    ldg256(z1, ob1 + i*ODIM);
    float4 v0  = *(const float4*)(uu0 + i*IDIM);
    float4 v1  = *(const float4*)(uu1 + i*IDIM);
    ull zp[8], up[4];
    #pragma unroll
    for (int q=0;q<8;q++) zp[q]=fpair(z0[q],z1[q]);
    up[0]=fpair(v0.x,v1.x);   up[1]=fpair(v0.y,v1.y);
    up[2]=fpair(v0.z,v1.z);   up[3]=fpair(v0.w,v1.w);

    const ulonglong2* M2 = (const ulonglong2*)&sM[mi*256];
    const ulonglong2* K2 = (const ulonglong2*)&sK[mi*128];
    const ulonglong2* N2 = (const ulonglong2*)&sN[mi*64];
    ull acc[SDIM];
    #pragma unroll
    for (int s=0;s<SDIM;s++){
      ulonglong2 k0p = K2[s*4+0];
      ull a = 0ull;
      ffma2(a, k0p.x, zp[0]); ffma2(a, k0p.y, zp[1]);
      ulonglong2 k1p = K2[s*4+1]; ffma2(a, k1p.x, zp[2]); ffma2(a, k1p.y, zp[3]);
      ulonglong2 k2p = K2[s*4+2]; ffma2(a, k2p.x, zp[4]); ffma2(a, k2p.y, zp[5]);
      ulonglong2 k3p = K2[s*4+3]; ffma2(a, k3p.x, zp[6]); ffma2(a, k3p.y, zp[7]);
      ulonglong2 n0p = N2[s*2+0]; ffma2(a, n0p.x, up[0]); ffma2(a, n0p.y, up[1]);
      ulonglong2 n1p = N2[s*2+1]; ffma2(a, n1p.x, up[2]); ffma2(a, n1p.y, up[3]);
      acc[s]=a;
    }
    #pragma unroll
    for (int s=0;s<SDIM;s++){
      ull a = acc[s];
      #pragma unroll
      for (int jj=0;jj<8;jj++){
        ulonglong2 mm = M2[s*8+jj];
        ffma2(a, mm.x, xp[2*jj]);
        ffma2(a, mm.y, xp[2*jj+1]);
      }
      acc[s]=a;
    }
    #pragma unroll
    for (int s=0;s<SDIM;s++) xp[s]=acc[s];

    {
      float a0[SDIM], a1[SDIM];
      #pragma unroll
      for (int s=0;s<SDIM;s++) unpack2(xp[s], a0[s], a1[s]);
      float* o0 = out + (((size_t)b0*T_SEQ) + (size_t)(k0+i))*SDIM;
      float* o1 = out + (((size_t)(b0+1)*T_SEQ) + (size_t)(k0+i))*SDIM;
      stg256(o0,     a0);
      stg256(o0 + 8, a0 + 8);
      stg256(o1,     a1);
      stg256(o1 + 8, a1 + 8);
    }
  }
}

extern "C" void kernel_launch(void* const* d_in, const int* in_sizes, int n_in,
                              void* d_out, int out_size)
{
  const float* obs = (const float*)d_in[0];
  const float* u   = (const float*)d_in[1];
  const float* A   = (const float*)d_in[2];
  const float* B   = (const float*)d_in[3];
  const float* C   = (const float*)d_in[4];
  const float* Q   = (const float*)d_in[5];
  const float* R   = (const float*)d_in[6];
  const float* x0  = (const float*)d_in[7];
  float* out = (float*)d_out;

  riccati_kernel<<<1, 256>>>(A, B, C, Q, R);

  dim3 gridResp(BATCH/(RTPB*NB), CH);
  resp_kernel<<<gridResp, RTPB>>>(obs, u);
  pass2_kernel<<<BATCH*SDIM/TPB, TPB>>>(x0);
  dim3 gridP3(BATCH/(TPB*NB), CH);
  pass3_kernel<<<gridP3, TPB>>>(obs, u, out);
}

// round 17
// speedup vs baseline: 1.0815x; 1.0815x over previous
#include <cuda_runtime.h>
#include <cstdint>
#include <cstddef>

#define BATCH 4096
#define T_SEQ 512
#define SDIM  16
#define ODIM  8
#define IDIM  4
#define RS    8
#define CH    64
#define LCH   8
#define NB    2
#define TPB   128
#define NTYPE 2

typedef unsigned long long ull;

__device__ float g_M [RS*256];
__device__ float g_Kg[RS*128];
__device__ float g_Ng[RS*64];
__device__ float g_Phi[NTYPE*256];
__device__ float g_W  [NTYPE*16*96];            // [type][s][j*12 + q] (q: 0..7 z, 8..11 u)
__device__ float g_d [(size_t)CH*SDIM*BATCH];   // [c][s][b]
__device__ float g_xs[(size_t)CH*SDIM*BATCH];   // [c][s][b]

// ---------- f32x2 helpers ----------
__device__ __forceinline__ ull fpair(float a, float b){
  ull r; asm("mov.b64 %0, {%1,%2};" : "=l"(r) : "f"(a), "f"(b)); return r;
}
__device__ __forceinline__ ull fdup(float a){ return fpair(a,a); }
__device__ __forceinline__ void unpack2(ull p, float& a, float& b){
  asm("mov.b64 {%0,%1}, %2;" : "=f"(a), "=f"(b) : "l"(p));
}
__device__ __forceinline__ void ffma2(ull& d, ull a, ull b){
  asm("fma.rn.f32x2 %0, %1, %2, %0;" : "+l"(d) : "l"(a), "l"(b));
}

// ---------- 256-bit global memory ops (sm_100+) ----------
__device__ __forceinline__ void ldg256(float* r, const float* p){
  asm("ld.global.v8.f32 {%0,%1,%2,%3,%4,%5,%6,%7}, [%8];"
      : "=f"(r[0]),"=f"(r[1]),"=f"(r[2]),"=f"(r[3]),
        "=f"(r[4]),"=f"(r[5]),"=f"(r[6]),"=f"(r[7])
      : "l"(p));
}
__device__ __forceinline__ void stg256(float* p, const float* r){
  asm volatile("st.global.v8.f32 [%0], {%1,%2,%3,%4,%5,%6,%7,%8};"
      :: "l"(p),
         "f"(r[0]),"f"(r[1]),"f"(r[2]),"f"(r[3]),
         "f"(r[4]),"f"(r[5]),"f"(r[6]),"f"(r[7])
      : "memory");
}

// K1: Riccati (8 exact steps) + W/Phi composition. 1 block, 256 threads.
// 8x8 S-inverse via Gauss-Jordan on warp 0 only (syncwarp-paced).
__global__ void riccati_kernel(const float* __restrict__ A_, const float* __restrict__ B_,
                               const float* __restrict__ C_, const float* __restrict__ Q_,
                               const float* __restrict__ R_)
{
  __shared__ float sA[256], sQ[256], sC[128], sB[64], sR[64], sCA[128], sCB[32];
  __shared__ float P[256], Tm[256], Pp[256], CP[128], S8[64], Inv8[64], KK[128];
  __shared__ float BufA[256], BufB[256];
  __shared__ float sMh[RS*256], sKh[RS*128], sNh[RS*64];
  const int t = threadIdx.x;
  const int s = t>>4, j = t&15;

  sA[t]=A_[t]; sQ[t]=Q_[t];
  P[t] = (s==j)?1.f:0.f;
  if (t<128) sC[t]=C_[t];
  if (t<64){ sB[t]=B_[t]; sR[t]=R_[t]; }
  __syncthreads();
  if (t<128){ int o=t>>4, jj=t&15; float a=0.f;
    #pragma unroll
    for(int m=0;m<16;m++) a+=sC[o*16+m]*sA[m*16+jj];
    sCA[t]=a; }
  if (t<32){ int o=t>>2, ii=t&3; float a=0.f;
    #pragma unroll
    for(int m=0;m<16;m++) a+=sC[o*16+m]*sB[m*4+ii];
    sCB[t]=a; }
  __syncthreads();

  for (int k=0;k<RS;k++){
    { float a=0.f;                                    // Tm = A @ P
      #pragma unroll
      for(int m=0;m<16;m++) a+=sA[s*16+m]*P[m*16+j];
      Tm[t]=a; }
    __syncthreads();
    { float a=sQ[t];                                  // Pp = Tm A^T + Q
      #pragma unroll
      for(int m=0;m<16;m++) a+=Tm[s*16+m]*sA[j*16+m];
      Pp[t]=a; }
    __syncthreads();
    if (t<128){ int o=t>>4, jj=t&15; float a=0.f;     // CP = C @ Pp
      #pragma unroll
      for(int m=0;m<16;m++) a+=sC[o*16+m]*Pp[m*16+jj];
      CP[t]=a; }
    __syncthreads();
    if (t<64){ int o=t>>3, p=t&7; float a=sR[t];      // S = CP C^T + R
      #pragma unroll
      for(int m=0;m<16;m++) a+=CP[o*16+m]*sC[p*16+m];
      S8[t]=a;
      Inv8[t]=(o==p)?1.f:0.f; }
    __syncthreads();
    // --- Gauss-Jordan inverse of S8 on warp 0: lane owns elements t and t+32.
    if (t<32){
      const int r0 = t>>3, c0 = t&7;                  // element t    : row r0,   col c0
      const int r1 = r0+4;                            // element t+32 : row r0+4, col c0
      #pragma unroll
      for (int p=0;p<8;p++){
        float rp = 1.f/S8[p*8+p];
        __syncwarp();
        if (r0==p){ S8[t]*=rp;    Inv8[t]*=rp; }
        if (r1==p){ S8[t+32]*=rp; Inv8[t+32]*=rp; }
        __syncwarp();
        float spc=S8[p*8+c0], sic=Inv8[p*8+c0];       // scaled pivot row
        float f0=S8[r0*8+p],  f1=S8[r1*8+p];
        __syncwarp();
        if (r0!=p){ S8[t]   -=f0*spc; Inv8[t]   -=f0*sic; }
        if (r1!=p){ S8[t+32]-=f1*spc; Inv8[t+32]-=f1*sic; }
        __syncwarp();
      }
    }
    __syncthreads();
    if (t<128){ int ss=t>>3, o=t&7; float a=0.f;      // K = CP^T Sinv
      #pragma unroll
      for(int p=0;p<8;p++) a+=CP[p*16+ss]*Inv8[p*8+o];
      KK[t]=a; }
    __syncthreads();
    { float a=Pp[t], mg=sA[t];                        // P_post, M_k
      #pragma unroll
      for(int o=0;o<8;o++){ float kv=KK[s*8+o]; a-=kv*CP[o*16+j]; mg-=kv*sCA[o*16+j]; }
      P[t]=a;
      sMh[k*256+t]=mg; g_M[k*256+t]=mg; }
    if (t<128){ sKh[k*128+t]=KK[t]; g_Kg[k*128+t]=KK[t]; }
    if (t<64){ int ss=t>>2, ii=t&3; float a=sB[t];    // N_k
      #pragma unroll
      for(int o=0;o<8;o++) a-=KK[ss*8+o]*sCB[o*4+ii];
      sNh[k*64+t]=a; g_Ng[k*64+t]=a; }
    __syncthreads();
  }

  for (int tt=0; tt<NTYPE; tt++){                     // W + Phi per chunk type
    float* Sb = BufA; float* Sn = BufB;
    Sb[t] = (s==j)?1.f:0.f;
    __syncthreads();
    for (int jj=LCH-1; jj>=0; jj--){
      const int k = (tt==0)? jj : (RS-1);
      if (t<128){ int ss=t>>3, o=t&7; float a=0.f;    // Wz
        #pragma unroll
        for(int m=0;m<16;m++) a+=Sb[ss*16+m]*sKh[k*128+m*8+o];
        g_W[(tt*16+ss)*96 + jj*12 + o] = a; }
      else { int e=t-128; int ss=e>>2, ii=e&3;        // Wu
        if (e<64){ float a=0.f;
          #pragma unroll
          for(int m=0;m<16;m++) a+=Sb[ss*16+m]*sNh[k*64+m*4+ii];
          g_W[(tt*16+ss)*96 + jj*12 + 8 + ii] = a; } }
      { float a=0.f;                                  // S = S @ M_k
        #pragma unroll
        for(int m=0;m<16;m++) a+=Sb[s*16+m]*sMh[k*256+m*16+j];
        Sn[t]=a; }
      __syncthreads();
      float* tmp=Sb; Sb=Sn; Sn=tmp;
    }
    g_Phi[tt*256+t]=Sb[t];
    __syncthreads();
  }
}

// P1 (R15 body): chunk response from zero state; z via v8 loads, u paired over 2 steps.
__global__ void __launch_bounds__(TPB) resp_kernel(const float* __restrict__ obs,
                                                   const float* __restrict__ u)
{
  __shared__ ull sW[16*96];
  const int c  = blockIdx.y;
  const int tt = (c==0)?0:1;
  for (int idx=threadIdx.x; idx<16*96; idx+=TPB)
    sW[idx] = fdup(g_W[tt*16*96 + idx]);
  const int b0 = (blockIdx.x*TPB + threadIdx.x)*NB;
  const int k0 = c*LCH;
  ull acc[SDIM];
  #pragma unroll
  for (int s=0;s<SDIM;s++) acc[s]=0ull;
  __syncthreads();

  const float* ob0 = obs + ((size_t)b0*T_SEQ + k0)*ODIM;
  const float* ob1 = ob0 + (size_t)T_SEQ*ODIM;
  const float* uu0 = u   + ((size_t)b0*T_SEQ + k0)*IDIM;
  const float* uu1 = uu0 + (size_t)T_SEQ*IDIM;

  for (int jj=0;jj<LCH;jj+=2){
    float ua0[8], ua1[8];
    ldg256(ua0, uu0 + jj*IDIM);
    ldg256(ua1, uu1 + jj*IDIM);
    #pragma unroll
    for (int h=0;h<2;h++){
      const int j2 = jj+h;
      float z0[8], z1[8];
      ldg256(z0, ob0 + j2*ODIM);
      ldg256(z1, ob1 + j2*ODIM);
      ull ip[12];
      #pragma unroll
      for (int q=0;q<8;q++) ip[q]=fpair(z0[q],z1[q]);
      #pragma unroll
      for (int q=0;q<4;q++) ip[8+q]=fpair(ua0[h*4+q],ua1[h*4+q]);
      #pragma unroll
      for (int s=0;s<SDIM;s++){
        const ulonglong2* Wr = (const ulonglong2*)&sW[s*96 + j2*12];
        ull a = acc[s];
        #pragma unroll
        for (int q=0;q<6;q++){
          ulonglong2 w = Wr[q];
          ffma2(a, w.x, ip[2*q]);
          ffma2(a, w.y, ip[2*q+1]);
        }
        acc[s]=a;
      }
    }
  }
  #pragma unroll
  for (int s=0;s<SDIM;s++)
    *(ull*)&g_d[((size_t)(c*SDIM+s))*BATCH + b0] = acc[s];
}

// P2 (R15 body): one thread per (batch, state).
__global__ void __launch_bounds__(TPB) pass2_kernel(const float* __restrict__ x0)
{
  __shared__ float sPhi[NTYPE*256];
  __shared__ float sX[TPB];
  for (int e=threadIdx.x; e<NTYPE*256; e+=TPB) sPhi[e]=g_Phi[e];
  const int t  = threadIdx.x;
  const int s  = t>>3;
  const int bl = t&7;
  const int b  = blockIdx.x*8 + bl;
  float x = x0[s];
  __syncthreads();
  g_xs[(size_t)s*BATCH + b] = x;
  for (int c=1;c<CH;c++){
    sX[s*8+bl] = x;
    const float* Phi = &sPhi[((c-1==0)?0:1)*256 + s*16];
    float dd = g_d[((size_t)((c-1)*16+s))*BATCH + b];
    __syncthreads();
    float a = dd;
    #pragma unroll
    for (int jj=0;jj<16;jj++) a += Phi[jj]*sX[jj*8+bl];
    __syncthreads();
    x = a;
    g_xs[((size_t)(c*16+s))*BATCH + b] = x;
  }
}

// P3 (R15/R14 body, verbatim): v8 z loads + v8 output stores, 4 blocks/SM.
__global__ void __launch_bounds__(TPB, 4) pass3_kernel(const float* __restrict__ obs,
                                                       const float* __restrict__ u,
                                                       float* __restrict__ out)
{
  __shared__ ull sM[LCH*256], sK[LCH*128], sN[LCH*64];  // 28KB
  const int tid = threadIdx.x;
  const int c  = blockIdx.y;
  const bool trans = (c==0);
  const int nset = trans ? LCH : 1;
  for (int idx=tid; idx<nset*256; idx+=TPB){
    int i=idx>>8, e=idx&255; int kk = trans ? i : (RS-1);
    sM[idx]=fdup(g_M[kk*256+e]);
  }
  for (int idx=tid; idx<nset*128; idx+=TPB){
    int i=idx>>7, e=idx&127; int kk = trans ? i : (RS-1);
    sK[idx]=fdup(g_Kg[kk*128+e]);
  }
  for (int idx=tid; idx<nset*64; idx+=TPB){
    int i=idx>>6, e=idx&63; int kk = trans ? i : (RS-1);
    sN[idx]=fdup(g_Ng[kk*64+e]);
  }
  const int b0 = blockIdx.x*(TPB*NB) + tid*NB;
  const int k0 = c*LCH;
  ull xp[SDIM];
  #pragma unroll
  for (int s=0;s<SDIM;s++)
    xp[s] = *(const ull*)&g_xs[((size_t)(c*SDIM+s))*BATCH + b0];
  __syncthreads();

  const float* ob0 = obs + ((size_t)b0*T_SEQ + k0)*ODIM;
  const float* ob1 = ob0 + (size_t)T_SEQ*ODIM;
  const float* uu0 = u   + ((size_t)b0*T_SEQ + k0)*IDIM;
  const float* uu1 = uu0 + (size_t)T_SEQ*IDIM;

  for (int i=0;i<LCH;i++){
    const int mi = trans ? i : 0;
    float z0[8], z1[8];
    ldg256(z0, ob0 + i*ODIM);
    ldg256(z1, ob1 + i*ODIM);
    float4 v0  = *(const float4*)(uu0 + i*IDIM);
    float4 v1  = *(const float4*)(uu1 + i*IDIM);
    ull zp[8], up[4];
    #pragma unroll
    for (int q=0;q<8;q++) zp[q]=fpair(z0[q],z1[q]);
    up[0]=fpair(v0.x,v1.x);   up[1]=fpair(v0.y,v1.y);
    up[2]=fpair(v0.z,v1.z);   up[3]=fpair(v0.w,v1.w);

    const ulonglong2* M2 = (const ulonglong2*)&sM[mi*256];
    const ulonglong2* K2 = (const ulonglong2*)&sK[mi*128];
    const ulonglong2* N2 = (const ulonglong2*)&sN[mi*64];
    ull acc[SDIM];
    #pragma unroll
    for (int s=0;s<SDIM;s++){
      ulonglong2 k0p = K2[s*4+0];
      ull a = 0ull;
      ffma2(a, k0p.x, zp[0]); ffma2(a, k0p.y, zp[1]);
      ulonglong2 k1p = K2[s*4+1]; ffma2(a, k1p.x, zp[2]); ffma2(a, k1p.y, zp[3]);
      ulonglong2 k2p = K2[s*4+2]; ffma2(a, k2p.x, zp[4]); ffma2(a, k2p.y, zp[5]);
      ulonglong2 k3p = K2[s*4+3]; ffma2(a, k3p.x, zp[6]); ffma2(a, k3p.y, zp[7]);
      ulonglong2 n0p = N2[s*2+0]; ffma2(a, n0p.x, up[0]); ffma2(a, n0p.y, up[1]);
      ulonglong2 n1p = N2[s*2+1]; ffma2(a, n1p.x, up[2]); ffma2(a, n1p.y, up[3]);
      acc[s]=a;
    }
    #pragma unroll
    for (int s=0;s<SDIM;s++){
      ull a = acc[s];
      #pragma unroll
      for (int jj=0;jj<8;jj++){
        ulonglong2 mm = M2[s*8+jj];
        ffma2(a, mm.x, xp[2*jj]);
        ffma2(a, mm.y, xp[2*jj+1]);
      }
      acc[s]=a;
    }
    #pragma unroll
    for (int s=0;s<SDIM;s++) xp[s]=acc[s];

    {
      float a0[SDIM], a1[SDIM];
      #pragma unroll
      for (int s=0;s<SDIM;s++) unpack2(xp[s], a0[s], a1[s]);
      float* o0 = out + (((size_t)b0*T_SEQ) + (size_t)(k0+i))*SDIM;
      float* o1 = out + (((size_t)(b0+1)*T_SEQ) + (size_t)(k0+i))*SDIM;
      stg256(o0,     a0);
      stg256(o0 + 8, a0 + 8);
      stg256(o1,     a1);
      stg256(o1 + 8, a1 + 8);
    }
  }
}

extern "C" void kernel_launch(void* const* d_in, const int* in_sizes, int n_in,
                              void* d_out, int out_size)
{
  const float* obs = (const float*)d_in[0];
  const float* u   = (const float*)d_in[1];
  const float* A   = (const float*)d_in[2];
  const float* B   = (const float*)d_in[3];
  const float* C   = (const float*)d_in[4];
  const float* Q   = (const float*)d_in[5];
  const float* R   = (const float*)d_in[6];
  const float* x0  = (const float*)d_in[7];
  float* out = (float*)d_out;

  riccati_kernel<<<1, 256>>>(A, B, C, Q, R);

  dim3 gridR(BATCH/(TPB*NB), CH);
  resp_kernel<<<gridR, TPB>>>(obs, u);
  pass2_kernel<<<BATCH*SDIM/TPB, TPB>>>(x0);
  pass3_kernel<<<gridR, TPB>>>(obs, u, out);
}